// round 4
// baseline (speedup 1.0000x reference)
#include <cuda_runtime.h>
#include <cuda_bf16.h>
#include <cstdint>

// CrossAttention_86165633892747 — collapses algebraically:
//   softmax over a size-1 axis == 1  =>  attn == v
//   out = chem @ (Wout @ Wv)^T + (Wout @ bv + bout)
// Single 16x16 affine map of chem_16. fp_16 / Wq / Wk are dead.

#define DIMC 16

// Folded matrix, laid out for packed f32x2 FMA:
//   g_Mp[in][p] = ( M[2p][in], M[2p+1][in] )   (in = input col, p = output pair)
//   g_c2[p]     = ( c[2p], c[2p+1] )
__device__ float2 g_Mp[DIMC][DIMC / 2];
__device__ float2 g_c2[DIMC / 2];

__global__ void ca_setup_kernel(const float* __restrict__ in_w,   // [48,16]
                                const float* __restrict__ in_b,   // [48]
                                const float* __restrict__ out_w,  // [16,16]
                                const float* __restrict__ out_b)  // [16]
{
    __shared__ float sM[DIMC][DIMC];
    const int t = threadIdx.x;              // 0..255
    const int o = t >> 4;                   // output row
    const int i = t & 15;                   // input col
    const float* Wv = in_w + 2 * DIMC * DIMC;   // rows 32..47
    const float* bv = in_b + 2 * DIMC;

    // M[o][i] = sum_k Wout[o][k] * Wv[k][i]
    float s = 0.f;
#pragma unroll
    for (int k = 0; k < DIMC; ++k)
        s = fmaf(out_w[o * DIMC + k], Wv[k * DIMC + i], s);
    sM[o][i] = s;
    __syncthreads();

    if (t < DIMC * (DIMC / 2)) {            // t = in*8 + p
        int in = t >> 3, p = t & 7;
        g_Mp[in][p] = make_float2(sM[2 * p][in], sM[2 * p + 1][in]);
    }
    if (t < DIMC / 2) {
        float c0 = out_b[2 * t], c1 = out_b[2 * t + 1];
#pragma unroll
        for (int k = 0; k < DIMC; ++k) {
            c0 = fmaf(out_w[(2 * t)     * DIMC + k], bv[k], c0);
            c1 = fmaf(out_w[(2 * t + 1) * DIMC + k], bv[k], c1);
        }
        g_c2[t] = make_float2(c0, c1);
    }
}

// ---- packed f32x2 helpers (FFMA2 is PTX-only; ptxas won't auto-fuse) ----
__device__ __forceinline__ unsigned long long bcast2(float x) {
    unsigned long long r;
    asm("mov.b64 %0, {%1, %1};" : "=l"(r) : "f"(x));
    return r;
}
__device__ __forceinline__ unsigned long long ffma2(unsigned long long a,
                                                    unsigned long long b,
                                                    unsigned long long c) {
    unsigned long long d;
    asm("fma.rn.f32x2 %0, %1, %2, %3;" : "=l"(d) : "l"(a), "l"(b), "l"(c));
    return d;
}
__device__ __forceinline__ float2 unpack2(unsigned long long v) {
    float2 r;
    asm("mov.b64 {%0, %1}, %2;" : "=f"(r.x), "=f"(r.y) : "l"(v));
    return r;
}

__global__ void __launch_bounds__(256, 8)
ca_apply_kernel(const float* __restrict__ x,  // chem_16 [B,16]
                float* __restrict__ out,      // [B,16]
                unsigned int nrows)
{
    __shared__ unsigned long long sM[DIMC][DIMC / 2];  // 1 KB
    __shared__ unsigned long long sc[DIMC / 2];

    const int t = threadIdx.x;
    if (t < DIMC * (DIMC / 2)) {
        float2 v = g_Mp[t >> 3][t & 7];
        unsigned long long p;
        asm("mov.b64 %0, {%1, %2};" : "=l"(p) : "f"(v.x), "f"(v.y));
        sM[t >> 3][t & 7] = p;
    } else if (t < DIMC * (DIMC / 2) + DIMC / 2) {
        float2 v = g_c2[t - DIMC * (DIMC / 2)];
        unsigned long long p;
        asm("mov.b64 %0, {%1, %2};" : "=l"(p) : "f"(v.x), "f"(v.y));
        sc[t - DIMC * (DIMC / 2)] = p;
    }
    __syncthreads();

    const unsigned int row = blockIdx.x * 256u + t;
    if (row >= nrows) return;
    const size_t base = (size_t)row * DIMC;

    // Streaming loads — zero reuse, working set >> L2.
    const float4* xp = reinterpret_cast<const float4*>(x + base);
    float4 x0 = __ldcs(xp + 0);
    float4 x1 = __ldcs(xp + 1);
    float4 x2 = __ldcs(xp + 2);
    float4 x3 = __ldcs(xp + 3);
    float xi[DIMC] = { x0.x, x0.y, x0.z, x0.w,  x1.x, x1.y, x1.z, x1.w,
                       x2.x, x2.y, x2.z, x2.w,  x3.x, x3.y, x3.z, x3.w };

    unsigned long long acc[DIMC / 2];
#pragma unroll
    for (int p = 0; p < DIMC / 2; ++p) acc[p] = sc[p];

#pragma unroll
    for (int i = 0; i < DIMC; ++i) {
        const unsigned long long xx = bcast2(xi[i]);
#pragma unroll
        for (int p = 0; p < DIMC / 2; ++p)
            acc[p] = ffma2(xx, sM[i][p], acc[p]);
    }

    float2 o0 = unpack2(acc[0]), o1 = unpack2(acc[1]);
    float2 o2 = unpack2(acc[2]), o3 = unpack2(acc[3]);
    float2 o4 = unpack2(acc[4]), o5 = unpack2(acc[5]);
    float2 o6 = unpack2(acc[6]), o7 = unpack2(acc[7]);

    float4* op = reinterpret_cast<float4*>(out + base);
    __stcs(op + 0, make_float4(o0.x, o0.y, o1.x, o1.y));
    __stcs(op + 1, make_float4(o2.x, o2.y, o3.x, o3.y));
    __stcs(op + 2, make_float4(o4.x, o4.y, o5.x, o5.y));
    __stcs(op + 3, make_float4(o6.x, o6.y, o7.x, o7.y));
}

extern "C" void kernel_launch(void* const* d_in, const int* in_sizes, int n_in,
                              void* d_out, int out_size)
{
    // inputs: 0=fp_16 (unused), 1=chem_16, 2=in_proj_weight, 3=in_proj_bias,
    //         4=out_proj_weight, 5=out_proj_bias
    const float* chem  = (const float*)d_in[1];
    const float* in_w  = (const float*)d_in[2];
    const float* in_b  = (const float*)d_in[3];
    const float* out_w = (const float*)d_in[4];
    const float* out_b = (const float*)d_in[5];
    float* out = (float*)d_out;

    const unsigned int nrows = (unsigned int)(in_sizes[1] / DIMC);

    ca_setup_kernel<<<1, 256>>>(in_w, in_b, out_w, out_b);

    const unsigned int blocks = (nrows + 255u) / 256u;
    ca_apply_kernel<<<blocks, 256>>>(chem, out, nrows);
}

// round 7
// speedup vs baseline: 1.1647x; 1.1647x over previous
#include <cuda_runtime.h>
#include <cuda_bf16.h>
#include <cstdint>

// CrossAttention_86165633892747 — collapses algebraically:
//   softmax over a size-1 axis == 1  =>  attn == v
//   out = chem @ (Wout @ Wv)^T + (Wout @ bv + bout)
// Single 16x16 affine map of chem_16. fp_16 / Wq / Wk are dead.
//
// R4 change: L1 was 87% (smem-crossbar bound: 128 LDS.64/row). Repack matrix
// for LDS.128 and process 2 rows/thread -> 16 LDS.128 per row (8x fewer
// wavefronts). Should shift bottleneck to DRAM.

#define DIMC 16

// g_M4[i][p2] = ( M[4p2][i], M[4p2+1][i], M[4p2+2][i], M[4p2+3][i] )
//   i = input col, output elements 4p2..4p2+3 (two f32x2 pairs per float4)
__device__ float4 g_M4[DIMC][DIMC / 4];
__device__ float2 g_c2[DIMC / 2];

__global__ void ca_setup_kernel(const float* __restrict__ in_w,   // [48,16]
                                const float* __restrict__ in_b,   // [48]
                                const float* __restrict__ out_w,  // [16,16]
                                const float* __restrict__ out_b)  // [16]
{
    __shared__ float sM[DIMC][DIMC];
    const int t = threadIdx.x;              // 0..255
    const int o = t >> 4;                   // output row
    const int i = t & 15;                   // input col
    const float* Wv = in_w + 2 * DIMC * DIMC;   // rows 32..47
    const float* bv = in_b + 2 * DIMC;

    // M[o][i] = sum_k Wout[o][k] * Wv[k][i]
    float s = 0.f;
#pragma unroll
    for (int k = 0; k < DIMC; ++k)
        s = fmaf(out_w[o * DIMC + k], Wv[k * DIMC + i], s);
    sM[o][i] = s;
    __syncthreads();

    if (t < DIMC * (DIMC / 4)) {            // t = in*4 + p2
        int in = t >> 2, p2 = t & 3;
        g_M4[in][p2] = make_float4(sM[4 * p2][in], sM[4 * p2 + 1][in],
                                   sM[4 * p2 + 2][in], sM[4 * p2 + 3][in]);
    }
    if (t < DIMC / 2) {
        float c0 = out_b[2 * t], c1 = out_b[2 * t + 1];
#pragma unroll
        for (int k = 0; k < DIMC; ++k) {
            c0 = fmaf(out_w[(2 * t)     * DIMC + k], bv[k], c0);
            c1 = fmaf(out_w[(2 * t + 1) * DIMC + k], bv[k], c1);
        }
        g_c2[t] = make_float2(c0, c1);
    }
}

// ---- packed f32x2 helpers (FFMA2 is PTX-only; ptxas won't auto-fuse) ----
__device__ __forceinline__ unsigned long long bcast2(float x) {
    unsigned long long r;
    asm("mov.b64 %0, {%1, %1};" : "=l"(r) : "f"(x));
    return r;
}
__device__ __forceinline__ unsigned long long ffma2(unsigned long long a,
                                                    unsigned long long b,
                                                    unsigned long long c) {
    unsigned long long d;
    asm("fma.rn.f32x2 %0, %1, %2, %3;" : "=l"(d) : "l"(a), "l"(b), "l"(c));
    return d;
}
__device__ __forceinline__ float2 unpack2(unsigned long long v) {
    float2 r;
    asm("mov.b64 {%0, %1}, %2;" : "=f"(r.x), "=f"(r.y) : "l"(v));
    return r;
}
__device__ __forceinline__ unsigned long long pack2(float lo, float hi) {
    unsigned long long r;
    asm("mov.b64 %0, {%1, %2};" : "=l"(r) : "f"(lo), "f"(hi));
    return r;
}

// 2 rows per thread; matrix read via LDS.128 (two f32x2 pairs per load),
// each load amortized over both rows: 16 LDS.128 per row.
__global__ void __launch_bounds__(256, 3)
ca_apply_kernel(const float* __restrict__ x,  // chem_16 [B,16]
                float* __restrict__ out,      // [B,16]
                unsigned int nrows)
{
    __shared__ float4 sM4[DIMC][DIMC / 4];             // 1 KB
    __shared__ unsigned long long sc[DIMC / 2];

    const int t = threadIdx.x;
    if (t < DIMC * (DIMC / 4)) {
        sM4[t >> 2][t & 3] = g_M4[t >> 2][t & 3];
    } else if (t < DIMC * (DIMC / 4) + DIMC / 2) {
        float2 v = g_c2[t - DIMC * (DIMC / 4)];
        sc[t - DIMC * (DIMC / 4)] = pack2(v.x, v.y);
    }
    __syncthreads();

    const unsigned int r0 = blockIdx.x * 512u + (unsigned int)t;
    const unsigned int r1 = r0 + 256u;
    const bool v0 = r0 < nrows;
    const bool v1 = r1 < nrows;
    if (!v0) return;

    // ---- load inputs (streaming: zero reuse, working set >> L2) ----
    float xa[DIMC], xb[DIMC];
    {
        const float4* xp = reinterpret_cast<const float4*>(x + (size_t)r0 * DIMC);
#pragma unroll
        for (int j = 0; j < 4; ++j) {
            float4 v = __ldcs(xp + j);
            xa[4 * j + 0] = v.x; xa[4 * j + 1] = v.y;
            xa[4 * j + 2] = v.z; xa[4 * j + 3] = v.w;
        }
    }
    if (v1) {
        const float4* xp = reinterpret_cast<const float4*>(x + (size_t)r1 * DIMC);
#pragma unroll
        for (int j = 0; j < 4; ++j) {
            float4 v = __ldcs(xp + j);
            xb[4 * j + 0] = v.x; xb[4 * j + 1] = v.y;
            xb[4 * j + 2] = v.z; xb[4 * j + 3] = v.w;
        }
    } else {
#pragma unroll
        for (int j = 0; j < DIMC; ++j) xb[j] = 0.f;
    }

    unsigned long long acc0[DIMC / 2], acc1[DIMC / 2];
#pragma unroll
    for (int p = 0; p < DIMC / 2; ++p) { acc0[p] = sc[p]; acc1[p] = sc[p]; }

#pragma unroll
    for (int i = 0; i < DIMC; ++i) {
        const unsigned long long xx0 = bcast2(xa[i]);
        const unsigned long long xx1 = bcast2(xb[i]);
#pragma unroll
        for (int p2 = 0; p2 < DIMC / 4; ++p2) {
            const ulonglong2 m =
                *reinterpret_cast<const ulonglong2*>(&sM4[i][p2]);  // LDS.128
            acc0[2 * p2 + 0] = ffma2(xx0, m.x, acc0[2 * p2 + 0]);
            acc0[2 * p2 + 1] = ffma2(xx0, m.y, acc0[2 * p2 + 1]);
            acc1[2 * p2 + 0] = ffma2(xx1, m.x, acc1[2 * p2 + 0]);
            acc1[2 * p2 + 1] = ffma2(xx1, m.y, acc1[2 * p2 + 1]);
        }
    }

    {
        float4* op = reinterpret_cast<float4*>(out + (size_t)r0 * DIMC);
#pragma unroll
        for (int j = 0; j < 4; ++j) {
            float2 a = unpack2(acc0[2 * j]), b = unpack2(acc0[2 * j + 1]);
            __stcs(op + j, make_float4(a.x, a.y, b.x, b.y));
        }
    }
    if (v1) {
        float4* op = reinterpret_cast<float4*>(out + (size_t)r1 * DIMC);
#pragma unroll
        for (int j = 0; j < 4; ++j) {
            float2 a = unpack2(acc1[2 * j]), b = unpack2(acc1[2 * j + 1]);
            __stcs(op + j, make_float4(a.x, a.y, b.x, b.y));
        }
    }
}

extern "C" void kernel_launch(void* const* d_in, const int* in_sizes, int n_in,
                              void* d_out, int out_size)
{
    // inputs: 0=fp_16 (unused), 1=chem_16, 2=in_proj_weight, 3=in_proj_bias,
    //         4=out_proj_weight, 5=out_proj_bias
    const float* chem  = (const float*)d_in[1];
    const float* in_w  = (const float*)d_in[2];
    const float* in_b  = (const float*)d_in[3];
    const float* out_w = (const float*)d_in[4];
    const float* out_b = (const float*)d_in[5];
    float* out = (float*)d_out;

    const unsigned int nrows = (unsigned int)(in_sizes[1] / DIMC);

    ca_setup_kernel<<<1, 256>>>(in_w, in_b, out_w, out_b);

    const unsigned int blocks = (nrows + 511u) / 512u;
    ca_apply_kernel<<<blocks, 256>>>(chem, out, nrows);
}

// round 8
// speedup vs baseline: 1.2013x; 1.0315x over previous
#include <cuda_runtime.h>
#include <cuda_bf16.h>
#include <cstdint>

// CrossAttention_86165633892747 — collapses algebraically:
//   softmax over a size-1 axis == 1  =>  attn == v
//   out = chem @ (Wout @ Wv)^T + (Wout @ bv + bout)
// Single 16x16 affine map of chem_16. fp_16 / Wq / Wk are dead.
//
// R4 change: L1 was 87% (smem-crossbar bound: 128 LDS.64/row). Repack matrix
// for LDS.128 and process 2 rows/thread -> 16 LDS.128 per row (8x fewer
// wavefronts). Should shift bottleneck to DRAM.

#define DIMC 16

// g_M4[i][p2] = ( M[4p2][i], M[4p2+1][i], M[4p2+2][i], M[4p2+3][i] )
//   i = input col, output elements 4p2..4p2+3 (two f32x2 pairs per float4)
__device__ float4 g_M4[DIMC][DIMC / 4];
__device__ float2 g_c2[DIMC / 2];

__global__ void ca_setup_kernel(const float* __restrict__ in_w,   // [48,16]
                                const float* __restrict__ in_b,   // [48]
                                const float* __restrict__ out_w,  // [16,16]
                                const float* __restrict__ out_b)  // [16]
{
    __shared__ float sM[DIMC][DIMC];
    const int t = threadIdx.x;              // 0..255
    const int o = t >> 4;                   // output row
    const int i = t & 15;                   // input col
    const float* Wv = in_w + 2 * DIMC * DIMC;   // rows 32..47
    const float* bv = in_b + 2 * DIMC;

    // M[o][i] = sum_k Wout[o][k] * Wv[k][i]
    float s = 0.f;
#pragma unroll
    for (int k = 0; k < DIMC; ++k)
        s = fmaf(out_w[o * DIMC + k], Wv[k * DIMC + i], s);
    sM[o][i] = s;
    __syncthreads();

    if (t < DIMC * (DIMC / 4)) {            // t = in*4 + p2
        int in = t >> 2, p2 = t & 3;
        g_M4[in][p2] = make_float4(sM[4 * p2][in], sM[4 * p2 + 1][in],
                                   sM[4 * p2 + 2][in], sM[4 * p2 + 3][in]);
    }
    if (t < DIMC / 2) {
        float c0 = out_b[2 * t], c1 = out_b[2 * t + 1];
#pragma unroll
        for (int k = 0; k < DIMC; ++k) {
            c0 = fmaf(out_w[(2 * t)     * DIMC + k], bv[k], c0);
            c1 = fmaf(out_w[(2 * t + 1) * DIMC + k], bv[k], c1);
        }
        g_c2[t] = make_float2(c0, c1);
    }
}

// ---- packed f32x2 helpers (FFMA2 is PTX-only; ptxas won't auto-fuse) ----
__device__ __forceinline__ unsigned long long bcast2(float x) {
    unsigned long long r;
    asm("mov.b64 %0, {%1, %1};" : "=l"(r) : "f"(x));
    return r;
}
__device__ __forceinline__ unsigned long long ffma2(unsigned long long a,
                                                    unsigned long long b,
                                                    unsigned long long c) {
    unsigned long long d;
    asm("fma.rn.f32x2 %0, %1, %2, %3;" : "=l"(d) : "l"(a), "l"(b), "l"(c));
    return d;
}
__device__ __forceinline__ float2 unpack2(unsigned long long v) {
    float2 r;
    asm("mov.b64 {%0, %1}, %2;" : "=f"(r.x), "=f"(r.y) : "l"(v));
    return r;
}
__device__ __forceinline__ unsigned long long pack2(float lo, float hi) {
    unsigned long long r;
    asm("mov.b64 %0, {%1, %2};" : "=l"(r) : "f"(lo), "f"(hi));
    return r;
}

// 2 rows per thread; matrix read via LDS.128 (two f32x2 pairs per load),
// each load amortized over both rows: 16 LDS.128 per row.
__global__ void __launch_bounds__(256, 3)
ca_apply_kernel(const float* __restrict__ x,  // chem_16 [B,16]
                float* __restrict__ out,      // [B,16]
                unsigned int nrows)
{
    __shared__ float4 sM4[DIMC][DIMC / 4];             // 1 KB
    __shared__ unsigned long long sc[DIMC / 2];

    const int t = threadIdx.x;
    if (t < DIMC * (DIMC / 4)) {
        sM4[t >> 2][t & 3] = g_M4[t >> 2][t & 3];
    } else if (t < DIMC * (DIMC / 4) + DIMC / 2) {
        float2 v = g_c2[t - DIMC * (DIMC / 4)];
        sc[t - DIMC * (DIMC / 4)] = pack2(v.x, v.y);
    }
    __syncthreads();

    const unsigned int r0 = blockIdx.x * 512u + (unsigned int)t;
    const unsigned int r1 = r0 + 256u;
    const bool v0 = r0 < nrows;
    const bool v1 = r1 < nrows;
    if (!v0) return;

    // ---- load inputs (streaming: zero reuse, working set >> L2) ----
    float xa[DIMC], xb[DIMC];
    {
        const float4* xp = reinterpret_cast<const float4*>(x + (size_t)r0 * DIMC);
#pragma unroll
        for (int j = 0; j < 4; ++j) {
            float4 v = __ldcs(xp + j);
            xa[4 * j + 0] = v.x; xa[4 * j + 1] = v.y;
            xa[4 * j + 2] = v.z; xa[4 * j + 3] = v.w;
        }
    }
    if (v1) {
        const float4* xp = reinterpret_cast<const float4*>(x + (size_t)r1 * DIMC);
#pragma unroll
        for (int j = 0; j < 4; ++j) {
            float4 v = __ldcs(xp + j);
            xb[4 * j + 0] = v.x; xb[4 * j + 1] = v.y;
            xb[4 * j + 2] = v.z; xb[4 * j + 3] = v.w;
        }
    } else {
#pragma unroll
        for (int j = 0; j < DIMC; ++j) xb[j] = 0.f;
    }

    unsigned long long acc0[DIMC / 2], acc1[DIMC / 2];
#pragma unroll
    for (int p = 0; p < DIMC / 2; ++p) { acc0[p] = sc[p]; acc1[p] = sc[p]; }

#pragma unroll
    for (int i = 0; i < DIMC; ++i) {
        const unsigned long long xx0 = bcast2(xa[i]);
        const unsigned long long xx1 = bcast2(xb[i]);
#pragma unroll
        for (int p2 = 0; p2 < DIMC / 4; ++p2) {
            const ulonglong2 m =
                *reinterpret_cast<const ulonglong2*>(&sM4[i][p2]);  // LDS.128
            acc0[2 * p2 + 0] = ffma2(xx0, m.x, acc0[2 * p2 + 0]);
            acc0[2 * p2 + 1] = ffma2(xx0, m.y, acc0[2 * p2 + 1]);
            acc1[2 * p2 + 0] = ffma2(xx1, m.x, acc1[2 * p2 + 0]);
            acc1[2 * p2 + 1] = ffma2(xx1, m.y, acc1[2 * p2 + 1]);
        }
    }

    {
        float4* op = reinterpret_cast<float4*>(out + (size_t)r0 * DIMC);
#pragma unroll
        for (int j = 0; j < 4; ++j) {
            float2 a = unpack2(acc0[2 * j]), b = unpack2(acc0[2 * j + 1]);
            __stcs(op + j, make_float4(a.x, a.y, b.x, b.y));
        }
    }
    if (v1) {
        float4* op = reinterpret_cast<float4*>(out + (size_t)r1 * DIMC);
#pragma unroll
        for (int j = 0; j < 4; ++j) {
            float2 a = unpack2(acc1[2 * j]), b = unpack2(acc1[2 * j + 1]);
            __stcs(op + j, make_float4(a.x, a.y, b.x, b.y));
        }
    }
}

extern "C" void kernel_launch(void* const* d_in, const int* in_sizes, int n_in,
                              void* d_out, int out_size)
{
    // inputs: 0=fp_16 (unused), 1=chem_16, 2=in_proj_weight, 3=in_proj_bias,
    //         4=out_proj_weight, 5=out_proj_bias
    const float* chem  = (const float*)d_in[1];
    const float* in_w  = (const float*)d_in[2];
    const float* in_b  = (const float*)d_in[3];
    const float* out_w = (const float*)d_in[4];
    const float* out_b = (const float*)d_in[5];
    float* out = (float*)d_out;

    const unsigned int nrows = (unsigned int)(in_sizes[1] / DIMC);

    ca_setup_kernel<<<1, 256>>>(in_w, in_b, out_w, out_b);

    const unsigned int blocks = (nrows + 511u) / 512u;
    ca_apply_kernel<<<blocks, 256>>>(chem, out, nrows);
}